// round 1
// baseline (speedup 1.0000x reference)
#include <cuda_runtime.h>

// RawStack: 10-layer dilated conv stack (WaveNet-style), fully fused.
//   layer i (d = 2^i):  h_new[t] = wh0*h[t] + wh1*h[t+d]
//                       x_new[t] = wx0*x[t] + wx1*x[t+d]
//                       x = tanh(h_new + x_new);  h = h_new
// Receptive field = 1024  ->  tile with 1023-element halo, all layers in SMEM.

#define N_LAYERS   10
#define T_IN       131072
#define HALO       1023                 // sum of dilations 1..512
#define T_OUT      (T_IN - HALO)        // 130049
#define TILE_OUT   4096
#define TILE_IN    (TILE_OUT + HALO)    // 5119
#define TILE_PAD   5120                 // padded buffer stride
#define THREADS    512
#define NTILES     ((T_OUT + TILE_OUT - 1) / TILE_OUT)   // 32
#define BATCH      64

// Accurate fast tanh: 1 - 2/(exp(2x)+1). ~1e-6 abs error; clamp avoids inf/inf.
__device__ __forceinline__ float fast_tanh(float v) {
    float xc = fminf(fmaxf(v, -15.0f), 15.0f);
    float e  = __expf(2.0f * xc);             // MUFU.EX2 path
    return 1.0f - __fdividef(2.0f, e + 1.0f); // MUFU.RCP path
}

__global__ __launch_bounds__(THREADS, 2)
void rawstack_kernel(const float* __restrict__ h,
                     const float* __restrict__ x,
                     const float* __restrict__ wh,
                     const float* __restrict__ wx,
                     float* __restrict__ out)
{
    extern __shared__ float sm[];
    float* hA = sm;
    float* hB = hA + TILE_PAD;
    float* xA = hB + TILE_PAD;
    float* xB = xA + TILE_PAD;
    float* w  = xB + TILE_PAD;   // 40 floats: wh[0..19], wx[0..19]

    const int tile  = blockIdx.x;
    const int b     = blockIdx.y;
    const int start = tile * TILE_OUT;
    const int tid   = threadIdx.x;

    // ---- load input tile (+halo) into SMEM, zero-pad past T_IN ----
    const float* hg = h + (size_t)b * T_IN + start;
    const float* xg = x + (size_t)b * T_IN + start;
    const int navail = T_IN - start;     // elements actually available
    #pragma unroll
    for (int j = tid; j < TILE_IN; j += THREADS) {
        const bool ok = (j < navail);
        hA[j] = ok ? hg[j] : 0.0f;
        xA[j] = ok ? xg[j] : 0.0f;
    }
    if (tid < 2 * N_LAYERS) {
        w[tid]                = wh[tid];
        w[tid + 2 * N_LAYERS] = wx[tid];
    }
    __syncthreads();

    // ---- 10 fused layers, ping-pong buffers ----
    float* hin  = hA; float* hout = hB;
    float* xin  = xA; float* xout = xB;
    int L = TILE_IN;

    #pragma unroll
    for (int i = 0; i < N_LAYERS; i++) {
        const int   d   = 1 << i;
        const float wh0 = w[2 * i],      wh1 = w[2 * i + 1];
        const float wx0 = w[20 + 2 * i], wx1 = w[20 + 2 * i + 1];
        const int   Lout = L - d;

        for (int t = tid; t < Lout; t += THREADS) {
            float hn = fmaf(wh0, hin[t], wh1 * hin[t + d]);
            float xn = fmaf(wx0, xin[t], wx1 * xin[t + d]);
            hout[t] = hn;
            xout[t] = fast_tanh(hn + xn);
        }
        __syncthreads();

        float* tp;
        tp = hin; hin = hout; hout = tp;
        tp = xin; xin = xout; xout = tp;
        L = Lout;
    }
    // L == TILE_OUT; xin holds final outputs for [start, start+TILE_OUT)

    // ---- store valid outputs ----
    float* og = out + (size_t)b * T_OUT;
    const int lim = min(TILE_OUT, T_OUT - start);
    for (int t = tid; t < lim; t += THREADS)
        og[start + t] = xin[t];
}

extern "C" void kernel_launch(void* const* d_in, const int* in_sizes, int n_in,
                              void* d_out, int out_size)
{
    const float* h  = (const float*)d_in[0];
    const float* x  = (const float*)d_in[1];
    const float* wh = (const float*)d_in[2];
    const float* wx = (const float*)d_in[3];
    float* out = (float*)d_out;

    const size_t smem_bytes = (size_t)(4 * TILE_PAD + 64) * sizeof(float);
    static bool attr_set = false;
    // cudaFuncSetAttribute executes immediately (not a stream op) -> capture-safe.
    cudaFuncSetAttribute(rawstack_kernel,
                         cudaFuncAttributeMaxDynamicSharedMemorySize,
                         (int)smem_bytes);

    dim3 grid(NTILES, BATCH);
    rawstack_kernel<<<grid, THREADS, smem_bytes>>>(h, x, wh, wx, out);
    (void)in_sizes; (void)n_in; (void)out_size; (void)attr_set;
}

// round 2
// speedup vs baseline: 1.2816x; 1.2816x over previous
#include <cuda_runtime.h>

// RawStack fused 10-layer dilated conv stack — register-resident version.
// Each lane holds 32 consecutive elements of h and x in registers.
// Layers 0-4 (d=1..16): contiguous layout, neighbor tail via shfl_down(1),
//   warp-boundary head via tiny SMEM exchange.
// XOR-swizzled warp-local SMEM transpose to strided layout (elem = r*32+lane).
// Layers 5-9 (d=32,64,128,256,512): d%32==0 -> in[t+d] is own-lane register
//   h[r + d/32]; only warp-boundary head (d elements) goes through SMEM.

#define T_IN     131072
#define HALO     1023
#define T_OUT    (T_IN - HALO)          // 130049
#define NW       8                      // warps per CTA
#define RR       32                     // elements per lane per array
#define WCH      (RR * 32)              // 1024 elements per warp
#define CTA_IN   (NW * WCH)             // 8192
#define TILE_OUT ((NW - 1) * WCH)       // 7168 (warp 7 = halo only)
#define NTILES   ((T_OUT + TILE_OUT - 1) / TILE_OUT)   // 19
#define THREADS  (NW * 32)              // 256
#define BATCH    64

struct Smem {
    float xchA[2][NW][32];     // phase-A head exchange: h at [0,16), x at [16,32)
    float xchB[2][NW][1024];   // phase-B exchange: h at [0,512), x at [512,1024)
                               // xchB[0][w] doubles as warp-local transpose buffer
};

// Accurate fast tanh: 1 - 2/(exp(2x)+1). ~1e-6 abs error.
__device__ __forceinline__ float fast_tanh(float v) {
    float xc = fminf(fmaxf(v, -15.0f), 15.0f);
    float e  = __expf(2.0f * xc);             // MUFU.EX2 path
    return 1.0f - __fdividef(2.0f, e + 1.0f); // MUFU.RCP path
}

// ---- Phase A layer (contiguous layout): d = 1<<I, I in [0,4] ----
template<int I>
__device__ __forceinline__ void layerA(float (&h)[RR], float (&x)[RR],
                                       Smem* sm, int w, int l,
                                       const float* __restrict__ wh,
                                       const float* __restrict__ wx)
{
    constexpr int D = 1 << I;      // 1..16
    constexpr int P = I & 1;
    const float wh0 = __ldg(&wh[2*I]), wh1 = __ldg(&wh[2*I+1]);
    const float wx0 = __ldg(&wx[2*I]), wx1 = __ldg(&wx[2*I+1]);

    // publish this warp's head [0,D) (pre-update values) for warp w-1
    if (l == 0) {
        #pragma unroll
        for (int j = 0; j < D; j++) {
            sm->xchA[P][w][j]      = h[j];
            sm->xchA[P][w][16 + j] = x[j];
        }
    }
    __syncthreads();

    // prefetch the D tail-neighbor values (pre-update!) before any update
    float nh[D], nx[D];
    #pragma unroll
    for (int j = 0; j < D; j++) {
        float vh = __shfl_down_sync(0xffffffffu, h[j], 1);
        float vx = __shfl_down_sync(0xffffffffu, x[j], 1);
        if (l == 31) {
            vh = (w < NW - 1) ? sm->xchA[P][w + 1][j]      : 0.0f;
            vx = (w < NW - 1) ? sm->xchA[P][w + 1][16 + j] : 0.0f;
        }
        nh[j] = vh; nx[j] = vx;
    }

    // in-place ascending update (in[t+d] not yet overwritten)
    #pragma unroll
    for (int r = 0; r < RR; r++) {
        float hd = (r + D < RR) ? h[r + D] : nh[r + D - RR];
        float xd = (r + D < RR) ? x[r + D] : nx[r + D - RR];
        float hn = fmaf(wh1, hd, wh0 * h[r]);
        float xn = fmaf(wx1, xd, wx0 * x[r]);
        h[r] = hn;
        x[r] = fast_tanh(hn + xn);
    }
}

// ---- Phase B layer (strided layout, elem = r*32 + lane): d = 32<<(I-5) ----
template<int I>
__device__ __forceinline__ void layerB(float (&h)[RR], float (&x)[RR],
                                       Smem* sm, int w, int l,
                                       const float* __restrict__ wh,
                                       const float* __restrict__ wx)
{
    constexpr int Q = 1 << (I - 5);    // d/32 = 1..16
    constexpr int P = I & 1;
    const float wh0 = __ldg(&wh[2*I]), wh1 = __ldg(&wh[2*I+1]);
    const float wx0 = __ldg(&wx[2*I]), wx1 = __ldg(&wx[2*I+1]);

    // publish head regs [0,Q) (all lanes) for warp w-1; bank-conflict-free
    #pragma unroll
    for (int j = 0; j < Q; j++) {
        sm->xchB[P][w][j * 32 + l]       = h[j];
        sm->xchB[P][w][512 + j * 32 + l] = x[j];
    }
    __syncthreads();

    float nh[Q], nx[Q];
    #pragma unroll
    for (int j = 0; j < Q; j++) {
        nh[j] = (w < NW - 1) ? sm->xchB[P][w + 1][j * 32 + l]       : 0.0f;
        nx[j] = (w < NW - 1) ? sm->xchB[P][w + 1][512 + j * 32 + l] : 0.0f;
    }

    #pragma unroll
    for (int r = 0; r < RR; r++) {
        float hd = (r + Q < RR) ? h[r + Q] : nh[r + Q - RR];
        float xd = (r + Q < RR) ? x[r + Q] : nx[r + Q - RR];
        float hn = fmaf(wh1, hd, wh0 * h[r]);
        float xn = fmaf(wx1, xd, wx0 * x[r]);
        h[r] = hn;
        x[r] = fast_tanh(hn + xn);
    }
}

// Warp-local contiguous -> strided transpose with XOR swizzle (conflict-free).
// elem e stored at tb[(e/32)*32 + ((e%32) ^ (e/32))].
__device__ __forceinline__ void transpose32(float (&v)[RR], float* tb, int l) {
    #pragma unroll
    for (int r = 0; r < RR; r++) tb[l * 32 + (r ^ l)] = v[r];  // write: banks r^l distinct
    __syncwarp();
    float t[RR];
    #pragma unroll
    for (int r = 0; r < RR; r++) t[r] = tb[r * 32 + (l ^ r)];  // read: banks l^r distinct
    __syncwarp();
    #pragma unroll
    for (int r = 0; r < RR; r++) v[r] = t[r];
}

__global__ __launch_bounds__(THREADS, 2)
void rawstack_kernel(const float* __restrict__ hg,
                     const float* __restrict__ xg,
                     const float* __restrict__ wh,
                     const float* __restrict__ wx,
                     float* __restrict__ out)
{
    extern __shared__ Smem smem_raw[];
    Smem* sm = smem_raw;

    const int tid = threadIdx.x;
    const int w   = tid >> 5;
    const int l   = tid & 31;
    const int tile = blockIdx.x;
    const int b    = blockIdx.y;

    // ---- load 32 consecutive elements per lane into registers ----
    const int in0 = tile * TILE_OUT + w * WCH + l * RR;
    const float* hp = hg + (size_t)b * T_IN + in0;
    const float* xp = xg + (size_t)b * T_IN + in0;

    float h[RR], x[RR];
    if (in0 + RR <= T_IN) {
        #pragma unroll
        for (int r = 0; r < RR; r += 4) {
            float4 a = *reinterpret_cast<const float4*>(hp + r);
            float4 c = *reinterpret_cast<const float4*>(xp + r);
            h[r] = a.x; h[r+1] = a.y; h[r+2] = a.z; h[r+3] = a.w;
            x[r] = c.x; x[r+1] = c.y; x[r+2] = c.z; x[r+3] = c.w;
        }
    } else {
        #pragma unroll
        for (int r = 0; r < RR; r++) {
            const bool ok = (in0 + r < T_IN);
            h[r] = ok ? hp[r] : 0.0f;
            x[r] = ok ? xp[r] : 0.0f;
        }
    }

    // ---- layers 0-4 (contiguous) ----
    layerA<0>(h, x, sm, w, l, wh, wx);
    layerA<1>(h, x, sm, w, l, wh, wx);
    layerA<2>(h, x, sm, w, l, wh, wx);
    layerA<3>(h, x, sm, w, l, wh, wx);
    layerA<4>(h, x, sm, w, l, wh, wx);

    // ---- transpose to strided layout (warp-local; reuses xchB[0][w]) ----
    float* tb = &sm->xchB[0][w][0];
    transpose32(h, tb, l);
    transpose32(x, tb, l);

    // ---- layers 5-9 (strided) ----
    layerB<5>(h, x, sm, w, l, wh, wx);
    layerB<6>(h, x, sm, w, l, wh, wx);
    layerB<7>(h, x, sm, w, l, wh, wx);
    layerB<8>(h, x, sm, w, l, wh, wx);
    layerB<9>(h, x, sm, w, l, wh, wx);

    // ---- store (strided layout -> coalesced STG per r) ----
    if (w < NW - 1) {
        const int obase = tile * TILE_OUT + w * WCH;
        float* op = out + (size_t)b * T_OUT + obase;
        #pragma unroll
        for (int r = 0; r < RR; r++) {
            const int g = obase + r * 32 + l;
            if (g < T_OUT) op[r * 32 + l] = x[r];
        }
    }
}

extern "C" void kernel_launch(void* const* d_in, const int* in_sizes, int n_in,
                              void* d_out, int out_size)
{
    const float* h  = (const float*)d_in[0];
    const float* x  = (const float*)d_in[1];
    const float* wh = (const float*)d_in[2];
    const float* wx = (const float*)d_in[3];
    float* out = (float*)d_out;

    const size_t smem_bytes = sizeof(Smem);   // ~66 KB
    cudaFuncSetAttribute(rawstack_kernel,
                         cudaFuncAttributeMaxDynamicSharedMemorySize,
                         (int)smem_bytes);

    dim3 grid(NTILES, BATCH);
    rawstack_kernel<<<grid, THREADS, smem_bytes>>>(h, x, wh, wx, out);
    (void)in_sizes; (void)n_in; (void)out_size;
}

// round 3
// speedup vs baseline: 1.9269x; 1.5034x over previous
#include <cuda_runtime.h>

// RawStack fused 10-layer dilated conv stack — register-resident version.
// Each lane holds 32 consecutive elements of h and x in registers.
// Layers 0-4 (d=1..16): contiguous layout, neighbor tail via shfl_down(1),
//   warp-boundary head via tiny SMEM exchange.
// XOR-swizzled warp-local SMEM transpose to strided layout (elem = r*32+lane).
// Layers 5-9 (d=32,64,128,256,512): d%32==0 -> in[t+d] is own-lane register
//   h[r + d/32]; only warp-boundary head goes through SMEM.
// R3 change: hardware MUFU tanh (tanh.approx.f32) — 1 MUFU instead of an
//   8-instruction accurate tanh. h-path is linear (tanh-free), so only the
//   x-path carries approximation error (~6e-4 abs, contractive propagation).

#define T_IN     131072
#define HALO     1023
#define T_OUT    (T_IN - HALO)          // 130049
#define NW       8                      // warps per CTA
#define RR       32                     // elements per lane per array
#define WCH      (RR * 32)              // 1024 elements per warp
#define CTA_IN   (NW * WCH)             // 8192
#define TILE_OUT ((NW - 1) * WCH)       // 7168 (warp 7 = halo only)
#define NTILES   ((T_OUT + TILE_OUT - 1) / TILE_OUT)   // 19
#define THREADS  (NW * 32)              // 256
#define BATCH    64

struct Smem {
    float xchA[2][NW][32];     // phase-A head exchange: h at [0,16), x at [16,32)
    float xchB[2][NW][1024];   // phase-B exchange: h at [0,512), x at [512,1024)
                               // xchB[0][w] doubles as warp-local transpose buffer
};

// Hardware tanh approximation (sm_75+ MUFU.TANH), single MUFU op.
__device__ __forceinline__ float fast_tanh(float v) {
    float r;
    asm("tanh.approx.f32 %0, %1;" : "=f"(r) : "f"(v));
    return r;
}

// ---- Phase A layer (contiguous layout): d = 1<<I, I in [0,4] ----
template<int I>
__device__ __forceinline__ void layerA(float (&h)[RR], float (&x)[RR],
                                       Smem* sm, int w, int l,
                                       const float* __restrict__ wh,
                                       const float* __restrict__ wx)
{
    constexpr int D = 1 << I;      // 1..16
    constexpr int P = I & 1;
    const float wh0 = __ldg(&wh[2*I]), wh1 = __ldg(&wh[2*I+1]);
    const float wx0 = __ldg(&wx[2*I]), wx1 = __ldg(&wx[2*I+1]);

    // publish this warp's head [0,D) (pre-update values) for warp w-1
    if (l == 0) {
        #pragma unroll
        for (int j = 0; j < D; j++) {
            sm->xchA[P][w][j]      = h[j];
            sm->xchA[P][w][16 + j] = x[j];
        }
    }
    __syncthreads();

    // prefetch the D tail-neighbor values (pre-update!) before any update
    float nh[D], nx[D];
    #pragma unroll
    for (int j = 0; j < D; j++) {
        float vh = __shfl_down_sync(0xffffffffu, h[j], 1);
        float vx = __shfl_down_sync(0xffffffffu, x[j], 1);
        if (l == 31) {
            vh = (w < NW - 1) ? sm->xchA[P][w + 1][j]      : 0.0f;
            vx = (w < NW - 1) ? sm->xchA[P][w + 1][16 + j] : 0.0f;
        }
        nh[j] = vh; nx[j] = vx;
    }

    // in-place ascending update (in[t+d] not yet overwritten)
    #pragma unroll
    for (int r = 0; r < RR; r++) {
        float hd = (r + D < RR) ? h[r + D] : nh[r + D - RR];
        float xd = (r + D < RR) ? x[r + D] : nx[r + D - RR];
        float hn = fmaf(wh1, hd, wh0 * h[r]);
        float xn = fmaf(wx1, xd, wx0 * x[r]);
        h[r] = hn;
        x[r] = fast_tanh(hn + xn);
    }
}

// ---- Phase B layer (strided layout, elem = r*32 + lane): d = 32<<(I-5) ----
template<int I>
__device__ __forceinline__ void layerB(float (&h)[RR], float (&x)[RR],
                                       Smem* sm, int w, int l,
                                       const float* __restrict__ wh,
                                       const float* __restrict__ wx)
{
    constexpr int Q = 1 << (I - 5);    // d/32 = 1..16
    constexpr int P = I & 1;
    const float wh0 = __ldg(&wh[2*I]), wh1 = __ldg(&wh[2*I+1]);
    const float wx0 = __ldg(&wx[2*I]), wx1 = __ldg(&wx[2*I+1]);

    // publish head regs [0,Q) (all lanes) for warp w-1; bank-conflict-free
    #pragma unroll
    for (int j = 0; j < Q; j++) {
        sm->xchB[P][w][j * 32 + l]       = h[j];
        sm->xchB[P][w][512 + j * 32 + l] = x[j];
    }
    __syncthreads();

    float nh[Q], nx[Q];
    #pragma unroll
    for (int j = 0; j < Q; j++) {
        nh[j] = (w < NW - 1) ? sm->xchB[P][w + 1][j * 32 + l]       : 0.0f;
        nx[j] = (w < NW - 1) ? sm->xchB[P][w + 1][512 + j * 32 + l] : 0.0f;
    }

    #pragma unroll
    for (int r = 0; r < RR; r++) {
        float hd = (r + Q < RR) ? h[r + Q] : nh[r + Q - RR];
        float xd = (r + Q < RR) ? x[r + Q] : nx[r + Q - RR];
        float hn = fmaf(wh1, hd, wh0 * h[r]);
        float xn = fmaf(wx1, xd, wx0 * x[r]);
        h[r] = hn;
        x[r] = fast_tanh(hn + xn);
    }
}

// Warp-local contiguous -> strided transpose with XOR swizzle (conflict-free).
// elem e stored at tb[(e/32)*32 + ((e%32) ^ (e/32))].
__device__ __forceinline__ void transpose32(float (&v)[RR], float* tb, int l) {
    #pragma unroll
    for (int r = 0; r < RR; r++) tb[l * 32 + (r ^ l)] = v[r];  // write: banks r^l distinct
    __syncwarp();
    float t[RR];
    #pragma unroll
    for (int r = 0; r < RR; r++) t[r] = tb[r * 32 + (l ^ r)];  // read: banks l^r distinct
    __syncwarp();
    #pragma unroll
    for (int r = 0; r < RR; r++) v[r] = t[r];
}

__global__ __launch_bounds__(THREADS, 2)
void rawstack_kernel(const float* __restrict__ hg,
                     const float* __restrict__ xg,
                     const float* __restrict__ wh,
                     const float* __restrict__ wx,
                     float* __restrict__ out)
{
    extern __shared__ Smem smem_raw[];
    Smem* sm = smem_raw;

    const int tid = threadIdx.x;
    const int w   = tid >> 5;
    const int l   = tid & 31;
    const int tile = blockIdx.x;
    const int b    = blockIdx.y;

    // ---- load 32 consecutive elements per lane into registers ----
    const int in0 = tile * TILE_OUT + w * WCH + l * RR;
    const float* hp = hg + (size_t)b * T_IN + in0;
    const float* xp = xg + (size_t)b * T_IN + in0;

    float h[RR], x[RR];
    if (in0 + RR <= T_IN) {
        #pragma unroll
        for (int r = 0; r < RR; r += 4) {
            float4 a = *reinterpret_cast<const float4*>(hp + r);
            float4 c = *reinterpret_cast<const float4*>(xp + r);
            h[r] = a.x; h[r+1] = a.y; h[r+2] = a.z; h[r+3] = a.w;
            x[r] = c.x; x[r+1] = c.y; x[r+2] = c.z; x[r+3] = c.w;
        }
    } else {
        #pragma unroll
        for (int r = 0; r < RR; r++) {
            const bool ok = (in0 + r < T_IN);
            h[r] = ok ? hp[r] : 0.0f;
            x[r] = ok ? xp[r] : 0.0f;
        }
    }

    // ---- layers 0-4 (contiguous) ----
    layerA<0>(h, x, sm, w, l, wh, wx);
    layerA<1>(h, x, sm, w, l, wh, wx);
    layerA<2>(h, x, sm, w, l, wh, wx);
    layerA<3>(h, x, sm, w, l, wh, wx);
    layerA<4>(h, x, sm, w, l, wh, wx);

    // ---- transpose to strided layout (warp-local; reuses xchB[0][w]) ----
    float* tb = &sm->xchB[0][w][0];
    transpose32(h, tb, l);
    transpose32(x, tb, l);

    // ---- layers 5-9 (strided) ----
    layerB<5>(h, x, sm, w, l, wh, wx);
    layerB<6>(h, x, sm, w, l, wh, wx);
    layerB<7>(h, x, sm, w, l, wh, wx);
    layerB<8>(h, x, sm, w, l, wh, wx);
    layerB<9>(h, x, sm, w, l, wh, wx);

    // ---- store (strided layout -> coalesced STG per r) ----
    if (w < NW - 1) {
        const int obase = tile * TILE_OUT + w * WCH;
        float* op = out + (size_t)b * T_OUT + obase;
        #pragma unroll
        for (int r = 0; r < RR; r++) {
            const int g = obase + r * 32 + l;
            if (g < T_OUT) op[r * 32 + l] = x[r];
        }
    }
}

extern "C" void kernel_launch(void* const* d_in, const int* in_sizes, int n_in,
                              void* d_out, int out_size)
{
    const float* h  = (const float*)d_in[0];
    const float* x  = (const float*)d_in[1];
    const float* wh = (const float*)d_in[2];
    const float* wx = (const float*)d_in[3];
    float* out = (float*)d_out;

    const size_t smem_bytes = sizeof(Smem);   // ~66 KB
    cudaFuncSetAttribute(rawstack_kernel,
                         cudaFuncAttributeMaxDynamicSharedMemorySize,
                         (int)smem_bytes);

    dim3 grid(NTILES, BATCH);
    rawstack_kernel<<<grid, THREADS, smem_bytes>>>(h, x, wh, wx, out);
    (void)in_sizes; (void)n_in; (void)out_size;
}